// round 10
// baseline (speedup 1.0000x reference)
#include <cuda_runtime.h>

#define D        32000
#define NV4      (D / 4)          // 8000
#define THREADS  512
#define NWARP    (THREADS / 32)
#define MAIN_ITERS 15             // 15*512 = 7680
#define TAILV4   (NV4 - MAIN_ITERS * THREADS)   // 320
#define CCAP     5888             // 47.4 KB static smem total; 4 CTAs/SM fit

__device__ __forceinline__ float warpSum(float v) {
#pragma unroll
    for (int o = 16; o > 0; o >>= 1) v += __shfl_down_sync(0xffffffffu, v, o);
    return v;
}
__device__ __forceinline__ float warpMax(float v) {
#pragma unroll
    for (int o = 16; o > 0; o >>= 1) v = fmaxf(v, __shfl_down_sync(0xffffffffu, v, o));
    return v;
}

struct Red {
    float red[NWARP][4];
    float bcast[4];
    int   cnt;
};

// Block-reduce 4 partial sums; results broadcast via r->bcast[0..3].
__device__ void reduce4(float s0, float s1, float s2, float s3,
                        Red* r, int lane, int wid) {
    s0 = warpSum(s0); s1 = warpSum(s1); s2 = warpSum(s2); s3 = warpSum(s3);
    if (lane == 0) {
        r->red[wid][0] = s0; r->red[wid][1] = s1;
        r->red[wid][2] = s2; r->red[wid][3] = s3;
    }
    __syncthreads();
    if (wid == 0) {
        float a = (lane < NWARP) ? r->red[lane][0] : 0.f;
        float b = (lane < NWARP) ? r->red[lane][1] : 0.f;
        float c = (lane < NWARP) ? r->red[lane][2] : 0.f;
        float d = (lane < NWARP) ? r->red[lane][3] : 0.f;
        a = warpSum(a); b = warpSum(b); c = warpSum(c); d = warpSum(d);
        if (lane == 0) {
            r->bcast[0] = a; r->bcast[1] = b; r->bcast[2] = c; r->bcast[3] = d;
        }
    }
    __syncthreads();
}

// Block max, broadcast via r->bcast[0].
__device__ void reduceMax(float m, Red* r, int lane, int wid) {
    m = warpMax(m);
    if (lane == 0) r->red[wid][0] = m;
    __syncthreads();
    if (wid == 0) {
        float t = (lane < NWARP) ? r->red[lane][0] : __int_as_float(0xff800000);
        t = warpMax(t);
        if (lane == 0) r->bcast[0] = t;
    }
    __syncthreads();
}

__device__ __forceinline__ void update_tau(float& tau_lo, float& tau_hi,
                                           float width, const Red* r) {
    // j_best = largest j in 1..4 with mass >= 1 (reference semantics)
    int jb = 0;
    if (r->bcast[0] >= 1.0f) jb = 1;
    if (r->bcast[1] >= 1.0f) jb = 2;
    if (r->bcast[2] >= 1.0f) jb = 3;
    if (r->bcast[3] >= 1.0f) jb = 4;
    tau_lo = tau_lo + (float)jb * width;
    tau_hi = tau_lo + width;
}

__global__ __launch_bounds__(THREADS, 4)
void entmax_kernel(const float* __restrict__ X, float* __restrict__ Y) {
    __shared__ float cvals[CCAP];
    __shared__ int   cidx[CCAP];
    __shared__ Red   r;

    const int tid  = threadIdx.x;
    const int lane = tid & 31;
    const int wid  = tid >> 5;
    const size_t rowoff = (size_t)blockIdx.x * D;
    const float4* __restrict__ xin4  = (const float4*)(X + rowoff);
    float4* __restrict__       yout4 = (float4*)(Y + rowoff);

    // ---- Phase 0: sample max over 8192 strided elements (4 float4/thread).
    //      sampleMax <= trueMax, so thr2 = sampleMax - 2 (raw-x units) gives a
    //      CONSERVATIVE capture threshold: {x > trueMax-2} ⊆ {x > thr2}.
    if (tid == 0) r.cnt = 0;
    float smax;
    {
        float4 a = xin4[tid];
        float4 b = xin4[tid + 2000];
        float4 c = xin4[tid + 4000];
        float4 d = xin4[tid + 6000];
        float m0 = fmaxf(fmaxf(a.x, a.y), fmaxf(a.z, a.w));
        float m1 = fmaxf(fmaxf(b.x, b.y), fmaxf(b.z, b.w));
        float m2 = fmaxf(fmaxf(c.x, c.y), fmaxf(c.z, c.w));
        float m3 = fmaxf(fmaxf(d.x, d.y), fmaxf(d.z, d.w));
        smax = fmaxf(fmaxf(m0, m1), fmaxf(m2, m3));
    }
    reduceMax(smax, &r, lane, wid);
    const float thr2 = r.bcast[0] - 2.0f;
    __syncthreads();   // r.red reuse below

    // ---- Phase 1 (ONLY full pass over X): stream read, zero-fill Y, true
    //      row max, and guarded atomic compaction of the superset.
    //      Extras (thr2 < 0.5x <= tau_final) contribute 0 to every probe
    //      mass and the normalizer, and scatter 0.0 over the zero-fill.
    float lmax = __int_as_float(0xff800000);  // -inf
    const float4 z4 = make_float4(0.f, 0.f, 0.f, 0.f);
#pragma unroll 5
    for (int i = 0; i < MAIN_ITERS; i++) {
        int k = tid + i * THREADS;
        float4 v = __ldcs(&xin4[k]);
        __stcs(&yout4[k], z4);
        float m4 = fmaxf(fmaxf(v.x, v.y), fmaxf(v.z, v.w));
        lmax = fmaxf(lmax, m4);
        if (m4 > thr2) {
            int k4 = 4 * k;
            if (v.x > thr2) { int p = atomicAdd(&r.cnt, 1); if (p < CCAP) { cvals[p] = 0.5f * v.x; cidx[p] = k4 + 0; } }
            if (v.y > thr2) { int p = atomicAdd(&r.cnt, 1); if (p < CCAP) { cvals[p] = 0.5f * v.y; cidx[p] = k4 + 1; } }
            if (v.z > thr2) { int p = atomicAdd(&r.cnt, 1); if (p < CCAP) { cvals[p] = 0.5f * v.z; cidx[p] = k4 + 2; } }
            if (v.w > thr2) { int p = atomicAdd(&r.cnt, 1); if (p < CCAP) { cvals[p] = 0.5f * v.w; cidx[p] = k4 + 3; } }
        }
    }
    if (tid < TAILV4) {
        int k = MAIN_ITERS * THREADS + tid;
        float4 v = __ldcs(&xin4[k]);
        __stcs(&yout4[k], z4);
        float m4 = fmaxf(fmaxf(v.x, v.y), fmaxf(v.z, v.w));
        lmax = fmaxf(lmax, m4);
        if (m4 > thr2) {
            int k4 = 4 * k;
            if (v.x > thr2) { int p = atomicAdd(&r.cnt, 1); if (p < CCAP) { cvals[p] = 0.5f * v.x; cidx[p] = k4 + 0; } }
            if (v.y > thr2) { int p = atomicAdd(&r.cnt, 1); if (p < CCAP) { cvals[p] = 0.5f * v.y; cidx[p] = k4 + 1; } }
            if (v.z > thr2) { int p = atomicAdd(&r.cnt, 1); if (p < CCAP) { cvals[p] = 0.5f * v.z; cidx[p] = k4 + 2; } }
            if (v.w > thr2) { int p = atomicAdd(&r.cnt, 1); if (p < CCAP) { cvals[p] = 0.5f * v.w; cidx[p] = k4 + 3; } }
        }
    }

    // ---- True row max -> tau bracket (reduceMax has the needed barriers)
    reduceMax(lmax, &r, lane, wid);
    const float mx = 0.5f * r.bcast[0];
    float tau_lo = mx - 1.0f;
    float tau_hi = mx - 0.005590169943749474f;   // (1/32000)^(alpha-1)
    const int cnt = r.cnt;
    __syncthreads();

    if (cnt <= CCAP) {
        // ---- All 5 bisection iterations on the compact set
        for (int it = 0; it < 5; it++) {
            float width = (tau_hi - tau_lo) / 5.0f;
            const float t1 = tau_lo + 1.0f * width;
            const float t2 = tau_lo + 2.0f * width;
            const float t3 = tau_lo + 3.0f * width;
            const float t4 = tau_lo + 4.0f * width;
            float s0 = 0.f, s1 = 0.f, s2 = 0.f, s3 = 0.f;
            for (int k = tid; k < cnt; k += THREADS) {
                float c = cvals[k];
                float d0 = fmaxf(c - t1, 0.f); s0 = fmaf(d0, d0, s0);
                float d1 = fmaxf(c - t2, 0.f); s1 = fmaf(d1, d1, s1);
                float d2 = fmaxf(c - t3, 0.f); s2 = fmaf(d2, d2, s2);
                float d3 = fmaxf(c - t4, 0.f); s3 = fmaf(d3, d3, s3);
            }
            reduce4(s0, s1, s2, s3, &r, lane, wid);
            update_tau(tau_lo, tau_hi, width, &r);
        }
        // ---- Normalizer from the compact set
        float s = 0.f;
        for (int k = tid; k < cnt; k += THREADS) {
            float d0 = fmaxf(cvals[k] - tau_lo, 0.f);
            s = fmaf(d0, d0, s);
        }
        reduce4(s, 0.f, 0.f, 0.f, &r, lane, wid);
        const float invS = 1.0f / r.bcast[0];
        const float tau  = tau_lo;

        // ---- Scatter (Y zero-filled in phase 1; reduce4's barriers ordered
        //      those CTA-local stores). Inactive extras write 0.0 over 0.0.
        float* __restrict__ yrow = (float*)(Y + rowoff);
        for (int k = tid; k < cnt; k += THREADS) {
            float d0 = fmaxf(cvals[k] - tau, 0.f);
            yrow[cidx[k]] = d0 * d0 * invS;
        }
    } else {
        // ---- Fallback (compact overflow, P~5e-8/row): full-row global passes
        for (int it = 0; it < 5; it++) {
            float width = (tau_hi - tau_lo) / 5.0f;
            const float t1 = tau_lo + 1.0f * width;
            const float t2 = tau_lo + 2.0f * width;
            const float t3 = tau_lo + 3.0f * width;
            const float t4 = tau_lo + 4.0f * width;
            float s0 = 0.f, s1 = 0.f, s2 = 0.f, s3 = 0.f;
            for (int k = tid; k < NV4; k += THREADS) {
                float4 v = xin4[k];
#define ACC(c)                                                        \
                {                                                     \
                    float cs = 0.5f * (c);                            \
                    float d0 = fmaxf(cs - t1, 0.f); s0 = fmaf(d0, d0, s0); \
                    float d1 = fmaxf(cs - t2, 0.f); s1 = fmaf(d1, d1, s1); \
                    float d2 = fmaxf(cs - t3, 0.f); s2 = fmaf(d2, d2, s2); \
                    float d3 = fmaxf(cs - t4, 0.f); s3 = fmaf(d3, d3, s3); \
                }
                ACC(v.x) ACC(v.y) ACC(v.z) ACC(v.w)
#undef ACC
            }
            reduce4(s0, s1, s2, s3, &r, lane, wid);
            update_tau(tau_lo, tau_hi, width, &r);
        }
        float s = 0.f;
        for (int k = tid; k < NV4; k += THREADS) {
            float4 v = xin4[k];
            float d0 = fmaxf(0.5f * v.x - tau_lo, 0.f); s = fmaf(d0, d0, s);
            float d1 = fmaxf(0.5f * v.y - tau_lo, 0.f); s = fmaf(d1, d1, s);
            float d2 = fmaxf(0.5f * v.z - tau_lo, 0.f); s = fmaf(d2, d2, s);
            float d3 = fmaxf(0.5f * v.w - tau_lo, 0.f); s = fmaf(d3, d3, s);
        }
        reduce4(s, 0.f, 0.f, 0.f, &r, lane, wid);
        const float invS = 1.0f / r.bcast[0];
        const float tau  = tau_lo;
        for (int k = tid; k < NV4; k += THREADS) {
            float4 v = xin4[k];
            float4 o;
            float d0 = fmaxf(0.5f * v.x - tau, 0.f); o.x = d0 * d0 * invS;
            float d1 = fmaxf(0.5f * v.y - tau, 0.f); o.y = d1 * d1 * invS;
            float d2 = fmaxf(0.5f * v.z - tau, 0.f); o.z = d2 * d2 * invS;
            float d3 = fmaxf(0.5f * v.w - tau, 0.f); o.w = d3 * d3 * invS;
            yout4[k] = o;
        }
    }
}

extern "C" void kernel_launch(void* const* d_in, const int* in_sizes, int n_in,
                              void* d_out, int out_size) {
    const float* X = (const float*)d_in[0];
    float* Y = (float*)d_out;
    const int rows = in_sizes[0] / D;   // 8192 for (4, 2048, 32000)
    entmax_kernel<<<rows, THREADS>>>(X, Y);
}

// round 11
// speedup vs baseline: 1.0083x; 1.0083x over previous
#include <cuda_runtime.h>

#define D        32000
#define NV4      (D / 4)          // 8000
#define THREADS  512
#define NWARP    (THREADS / 32)
#define MAIN_ITERS 15             // 15*512 = 7680
#define TAILV4   (NV4 - MAIN_ITERS * THREADS)   // 320
#define CCAP     5888             // 47.4 KB static smem total; 4 CTAs/SM fit

__device__ __forceinline__ float warpSum(float v) {
#pragma unroll
    for (int o = 16; o > 0; o >>= 1) v += __shfl_down_sync(0xffffffffu, v, o);
    return v;
}
__device__ __forceinline__ float warpMax(float v) {
#pragma unroll
    for (int o = 16; o > 0; o >>= 1) v = fmaxf(v, __shfl_down_sync(0xffffffffu, v, o));
    return v;
}

struct Red {
    float red[NWARP][4];
    float bcast[4];
    int   cnt;
};

// Block-reduce 4 partial sums; results broadcast via r->bcast[0..3].
__device__ void reduce4(float s0, float s1, float s2, float s3,
                        Red* r, int lane, int wid) {
    s0 = warpSum(s0); s1 = warpSum(s1); s2 = warpSum(s2); s3 = warpSum(s3);
    if (lane == 0) {
        r->red[wid][0] = s0; r->red[wid][1] = s1;
        r->red[wid][2] = s2; r->red[wid][3] = s3;
    }
    __syncthreads();
    if (wid == 0) {
        float a = (lane < NWARP) ? r->red[lane][0] : 0.f;
        float b = (lane < NWARP) ? r->red[lane][1] : 0.f;
        float c = (lane < NWARP) ? r->red[lane][2] : 0.f;
        float d = (lane < NWARP) ? r->red[lane][3] : 0.f;
        a = warpSum(a); b = warpSum(b); c = warpSum(c); d = warpSum(d);
        if (lane == 0) {
            r->bcast[0] = a; r->bcast[1] = b; r->bcast[2] = c; r->bcast[3] = d;
        }
    }
    __syncthreads();
}

// Block max, broadcast via r->bcast[0].
__device__ void reduceMax(float m, Red* r, int lane, int wid) {
    m = warpMax(m);
    if (lane == 0) r->red[wid][0] = m;
    __syncthreads();
    if (wid == 0) {
        float t = (lane < NWARP) ? r->red[lane][0] : __int_as_float(0xff800000);
        t = warpMax(t);
        if (lane == 0) r->bcast[0] = t;
    }
    __syncthreads();
}

__device__ __forceinline__ void update_tau(float& tau_lo, float& tau_hi,
                                           float width, const Red* r) {
    // j_best = largest j in 1..4 with mass >= 1 (reference semantics)
    int jb = 0;
    if (r->bcast[0] >= 1.0f) jb = 1;
    if (r->bcast[1] >= 1.0f) jb = 2;
    if (r->bcast[2] >= 1.0f) jb = 3;
    if (r->bcast[3] >= 1.0f) jb = 4;
    tau_lo = tau_lo + (float)jb * width;
    tau_hi = tau_lo + width;
}

__global__ __launch_bounds__(THREADS, 4)
void entmax_kernel(const float* __restrict__ X, float* __restrict__ Y) {
    __shared__ float cvals[CCAP];
    __shared__ int   cidx[CCAP];
    __shared__ Red   r;

    const int tid  = threadIdx.x;
    const int lane = tid & 31;
    const int wid  = tid >> 5;
    const size_t rowoff = (size_t)blockIdx.x * D;
    const float4* __restrict__ xin4  = (const float4*)(X + rowoff);
    float4* __restrict__       yout4 = (float4*)(Y + rowoff);

    // ---- Phase 0: sample max over 8192 strided elements (4 float4/thread).
    //      sampleMax <= trueMax, so thr2 = sampleMax - 2 (raw-x units) gives a
    //      CONSERVATIVE capture threshold: {x > trueMax-2} ⊆ {x > thr2}.
    if (tid == 0) r.cnt = 0;
    float smax;
    {
        float4 a = xin4[tid];
        float4 b = xin4[tid + 2000];
        float4 c = xin4[tid + 4000];
        float4 d = xin4[tid + 6000];
        float m0 = fmaxf(fmaxf(a.x, a.y), fmaxf(a.z, a.w));
        float m1 = fmaxf(fmaxf(b.x, b.y), fmaxf(b.z, b.w));
        float m2 = fmaxf(fmaxf(c.x, c.y), fmaxf(c.z, c.w));
        float m3 = fmaxf(fmaxf(d.x, d.y), fmaxf(d.z, d.w));
        smax = fmaxf(fmaxf(m0, m1), fmaxf(m2, m3));
    }
    reduceMax(smax, &r, lane, wid);
    const float thr2 = r.bcast[0] - 2.0f;
    __syncthreads();   // r.red reuse below

    // ---- Pass 1 (PURE READS): stream X once, true row max, and guarded
    //      atomic compaction of the superset {x > thr2} (~1000 elements).
    //      Extras (thr2 < 0.5x <= tau_final) contribute 0 to every probe
    //      mass and the normalizer, and scatter 0.0 over the zero-fill.
    float lmax = __int_as_float(0xff800000);  // -inf
#pragma unroll 5
    for (int i = 0; i < MAIN_ITERS; i++) {
        int k = tid + i * THREADS;
        float4 v = __ldcs(&xin4[k]);
        float m4 = fmaxf(fmaxf(v.x, v.y), fmaxf(v.z, v.w));
        lmax = fmaxf(lmax, m4);
        if (m4 > thr2) {
            int k4 = 4 * k;
            if (v.x > thr2) { int p = atomicAdd(&r.cnt, 1); if (p < CCAP) { cvals[p] = 0.5f * v.x; cidx[p] = k4 + 0; } }
            if (v.y > thr2) { int p = atomicAdd(&r.cnt, 1); if (p < CCAP) { cvals[p] = 0.5f * v.y; cidx[p] = k4 + 1; } }
            if (v.z > thr2) { int p = atomicAdd(&r.cnt, 1); if (p < CCAP) { cvals[p] = 0.5f * v.z; cidx[p] = k4 + 2; } }
            if (v.w > thr2) { int p = atomicAdd(&r.cnt, 1); if (p < CCAP) { cvals[p] = 0.5f * v.w; cidx[p] = k4 + 3; } }
        }
    }
    if (tid < TAILV4) {
        int k = MAIN_ITERS * THREADS + tid;
        float4 v = __ldcs(&xin4[k]);
        float m4 = fmaxf(fmaxf(v.x, v.y), fmaxf(v.z, v.w));
        lmax = fmaxf(lmax, m4);
        if (m4 > thr2) {
            int k4 = 4 * k;
            if (v.x > thr2) { int p = atomicAdd(&r.cnt, 1); if (p < CCAP) { cvals[p] = 0.5f * v.x; cidx[p] = k4 + 0; } }
            if (v.y > thr2) { int p = atomicAdd(&r.cnt, 1); if (p < CCAP) { cvals[p] = 0.5f * v.y; cidx[p] = k4 + 1; } }
            if (v.z > thr2) { int p = atomicAdd(&r.cnt, 1); if (p < CCAP) { cvals[p] = 0.5f * v.z; cidx[p] = k4 + 2; } }
            if (v.w > thr2) { int p = atomicAdd(&r.cnt, 1); if (p < CCAP) { cvals[p] = 0.5f * v.w; cidx[p] = k4 + 3; } }
        }
    }

    // ---- True row max -> tau bracket (reduceMax has the needed barriers)
    reduceMax(lmax, &r, lane, wid);
    const float mx = 0.5f * r.bcast[0];
    float tau_lo = mx - 1.0f;
    float tau_hi = mx - 0.005590169943749474f;   // (1/32000)^(alpha-1)
    const int cnt = r.cnt;
    __syncthreads();

    // ---- Pass 2 (PURE WRITES): zero-fill Y — no loads, max write BW.
    {
        const float4 z4 = make_float4(0.f, 0.f, 0.f, 0.f);
#pragma unroll 5
        for (int i = 0; i < MAIN_ITERS; i++) {
            __stcs(&yout4[tid + i * THREADS], z4);
        }
        if (tid < TAILV4) {
            __stcs(&yout4[MAIN_ITERS * THREADS + tid], z4);
        }
    }

    if (cnt <= CCAP) {
        // ---- All 5 bisection iterations on the compact set
        for (int it = 0; it < 5; it++) {
            float width = (tau_hi - tau_lo) / 5.0f;
            const float t1 = tau_lo + 1.0f * width;
            const float t2 = tau_lo + 2.0f * width;
            const float t3 = tau_lo + 3.0f * width;
            const float t4 = tau_lo + 4.0f * width;
            float s0 = 0.f, s1 = 0.f, s2 = 0.f, s3 = 0.f;
            for (int k = tid; k < cnt; k += THREADS) {
                float c = cvals[k];
                float d0 = fmaxf(c - t1, 0.f); s0 = fmaf(d0, d0, s0);
                float d1 = fmaxf(c - t2, 0.f); s1 = fmaf(d1, d1, s1);
                float d2 = fmaxf(c - t3, 0.f); s2 = fmaf(d2, d2, s2);
                float d3 = fmaxf(c - t4, 0.f); s3 = fmaf(d3, d3, s3);
            }
            reduce4(s0, s1, s2, s3, &r, lane, wid);
            update_tau(tau_lo, tau_hi, width, &r);
        }
        // ---- Normalizer from the compact set
        float s = 0.f;
        for (int k = tid; k < cnt; k += THREADS) {
            float d0 = fmaxf(cvals[k] - tau_lo, 0.f);
            s = fmaf(d0, d0, s);
        }
        reduce4(s, 0.f, 0.f, 0.f, &r, lane, wid);
        const float invS = 1.0f / r.bcast[0];
        const float tau  = tau_lo;

        // ---- Scatter (Y zero-filled above; reduce4's barriers ordered the
        //      CTA-local stores). Inactive extras write 0.0 over 0.0.
        float* __restrict__ yrow = (float*)(Y + rowoff);
        for (int k = tid; k < cnt; k += THREADS) {
            float d0 = fmaxf(cvals[k] - tau, 0.f);
            yrow[cidx[k]] = d0 * d0 * invS;
        }
    } else {
        // ---- Fallback (compact overflow, P~1e-7/row): full-row global passes.
        //      Overwrites the zero-fill with the dense result — unconditional.
        for (int it = 0; it < 5; it++) {
            float width = (tau_hi - tau_lo) / 5.0f;
            const float t1 = tau_lo + 1.0f * width;
            const float t2 = tau_lo + 2.0f * width;
            const float t3 = tau_lo + 3.0f * width;
            const float t4 = tau_lo + 4.0f * width;
            float s0 = 0.f, s1 = 0.f, s2 = 0.f, s3 = 0.f;
            for (int k = tid; k < NV4; k += THREADS) {
                float4 v = xin4[k];
#define ACC(c)                                                        \
                {                                                     \
                    float cs = 0.5f * (c);                            \
                    float d0 = fmaxf(cs - t1, 0.f); s0 = fmaf(d0, d0, s0); \
                    float d1 = fmaxf(cs - t2, 0.f); s1 = fmaf(d1, d1, s1); \
                    float d2 = fmaxf(cs - t3, 0.f); s2 = fmaf(d2, d2, s2); \
                    float d3 = fmaxf(cs - t4, 0.f); s3 = fmaf(d3, d3, s3); \
                }
                ACC(v.x) ACC(v.y) ACC(v.z) ACC(v.w)
#undef ACC
            }
            reduce4(s0, s1, s2, s3, &r, lane, wid);
            update_tau(tau_lo, tau_hi, width, &r);
        }
        float s = 0.f;
        for (int k = tid; k < NV4; k += THREADS) {
            float4 v = xin4[k];
            float d0 = fmaxf(0.5f * v.x - tau_lo, 0.f); s = fmaf(d0, d0, s);
            float d1 = fmaxf(0.5f * v.y - tau_lo, 0.f); s = fmaf(d1, d1, s);
            float d2 = fmaxf(0.5f * v.z - tau_lo, 0.f); s = fmaf(d2, d2, s);
            float d3 = fmaxf(0.5f * v.w - tau_lo, 0.f); s = fmaf(d3, d3, s);
        }
        reduce4(s, 0.f, 0.f, 0.f, &r, lane, wid);
        const float invS = 1.0f / r.bcast[0];
        const float tau  = tau_lo;
        for (int k = tid; k < NV4; k += THREADS) {
            float4 v = xin4[k];
            float4 o;
            float d0 = fmaxf(0.5f * v.x - tau, 0.f); o.x = d0 * d0 * invS;
            float d1 = fmaxf(0.5f * v.y - tau, 0.f); o.y = d1 * d1 * invS;
            float d2 = fmaxf(0.5f * v.z - tau, 0.f); o.z = d2 * d2 * invS;
            float d3 = fmaxf(0.5f * v.w - tau, 0.f); o.w = d3 * d3 * invS;
            yout4[k] = o;
        }
    }
}

extern "C" void kernel_launch(void* const* d_in, const int* in_sizes, int n_in,
                              void* d_out, int out_size) {
    const float* X = (const float*)d_in[0];
    float* Y = (float*)d_out;
    const int rows = in_sizes[0] / D;   // 8192 for (4, 2048, 32000)
    entmax_kernel<<<rows, THREADS>>>(X, Y);
}